// round 16
// baseline (speedup 1.0000x reference)
#include <cuda_runtime.h>
#include <cuda_bf16.h>
#include <cstdint>

// Problem constants
#define BATCH 32
#define CIN   64
#define HH    56
#define WW    56
#define NOUT  128
#define IMG   (HH*WW)          // 3136

// Tiling: CTA = 224 px (4 rows x 56) x 128 n, 28 warps as 7(M) x 4(N), warp 32x32
#define ROWS_PER_CTA 4
#define THREADS 896
#define LINE_B 144                      // 128B data + 16B pad: stride%128==16 -> ldmatrix conflict-free
#define IN_LINES (6*58)                 // halo tile lines
#define IN_SM_BYTES (IN_LINES*LINE_B)   // 50112
#define WFRAG_U32 (9*4*8*32*4)          // 36864 u32 = 147456 B
#define WFRAG_BYTES (WFRAG_U32*4)
#define SMEM_TOTAL (IN_SM_BYTES + WFRAG_BYTES)   // 197568

// Weights pre-packed in mma B-fragment order, two n8-tiles contiguous per lane:
// [kk][ks][np(8)][lane(32)][4] u32
//   j=0,1 -> n = np*16 + g     : { W[n][ks*16+kq*2], W[n][ks*16+8+kq*2] }
//   j=2,3 -> n = np*16 + 8 + g : same
__device__ uint32_t g_wq[WFRAG_U32];

__global__ void wprep_kernel(const float* __restrict__ w) {
    int idx = blockIdx.x * 256 + threadIdx.x;
    if (idx >= WFRAG_U32) return;
    int j    = idx & 3;
    int lane = (idx >> 2) & 31;
    int np   = (idx >> 7) & 7;
    int ks   = (idx >> 10) & 3;
    int kk   = idx >> 12;
    int g = lane >> 2, kq = lane & 3;
    int n = np * 16 + (j >> 1) * 8 + g;
    int c = ks * 16 + (j & 1) * 8 + kq * 2;
    // gmem weight layout [n][c][kh][kw]; RNE fp32->bf16 == float_quantize(8,7)
    __nv_bfloat16 lo = __float2bfloat16(w[(n * 64 + c) * 9 + kk]);
    __nv_bfloat16 hi = __float2bfloat16(w[(n * 64 + c + 1) * 9 + kk]);
    g_wq[idx] = (uint32_t)(*(const uint16_t*)&lo) |
                ((uint32_t)(*(const uint16_t*)&hi) << 16);
}

__global__ void __launch_bounds__(THREADS, 1)
conv_kernel(const float* __restrict__ in, const float* __restrict__ bias,
            float* __restrict__ out) {
    extern __shared__ char smb[];
    char* insmB = smb;
    char* wsmB  = smb + IN_SM_BYTES;

    const int ty   = blockIdx.x;     // 0..13  (group of 4 output rows)
    const int b    = blockIdx.y;     // 0..31
    const int tid  = threadIdx.x;
    const int lane = tid & 31;
    const int warp = tid >> 5;       // 0..27
    const int y0   = ty * ROWS_PER_CTA;

    // ---- weight fragments: async copy gmem->smem, overlapped with input stage
    {
        uint32_t wdst = (uint32_t)__cvta_generic_to_shared(wsmB);
        const char* wsrc = (const char*)g_wq;
        #pragma unroll
        for (int it = 0; it < 11; ++it) {
            int s = it * THREADS + tid;          // 9216 16B chunks
            if (s < WFRAG_BYTES / 16)
                asm volatile("cp.async.cg.shared.global [%0], [%1], 16;\n"
                             :: "r"(wdst + s * 16), "l"(wsrc + (size_t)s * 16));
        }
        asm volatile("cp.async.commit_group;\n");
    }

    // ---- stage input halo tile (fp32 -> bf16, linear padded layout) ---------
    {
        const float* inb = in + (size_t)b * CIN * IMG;
        #pragma unroll 4
        for (int it = 0; it < 28; ++it) {
            int s  = it * THREADS + tid;   // 0..24575
            if (s < 24576) {
                int r  = s >> 12;              // 0..5   (halo row, y = y0-1+r)
                int c  = (s >> 6) & 63;        // channel
                int xi = s & 63;               // halo col (x = xi-1), 58..63 unused
                int y  = y0 - 1 + r;
                int x  = xi - 1;
                float v = 0.f;
                if (y >= 0 && y < HH && x >= 0 && x < WW)
                    v = inb[c * IMG + y * WW + x];
                if (xi < 58) {
                    int line = r * 58 + xi;
                    *(__nv_bfloat16*)(insmB + line * LINE_B + c * 2) =
                        __float2bfloat16(v);
                }
            }
        }
    }

    // ---- warp tiling: 7(M) x 4(N), warp tile 32px x 32n ---------------------
    const int warpN = warp & 3;        // 0..3 -> 32 channels each
    const int warpM = warp >> 2;       // 0..6 -> 32 px each (all real)
    const int g  = lane >> 2;          // 0..7
    const int kq = lane & 3;           // 0..3
    const int rl = lane & 15;          // ldmatrix row within 16-row A tile
    const int hi16 = ((lane >> 4) & 1) << 4;   // k-half select for ldmatrix ptr

    const uint32_t insm32 = (uint32_t)__cvta_generic_to_shared(insmB);
    // per-(kk,ks) B block base for this warp/lane: [kk*4+ks][np][lane][4] u32
    const uint32_t* wfrW = (const uint32_t*)wsmB + ((warpN * 2) * 32 + lane) * 4;

    // bias (bf16-quantized) hoisted: n0 = warpN*32 + ni*8 + kq*2
    float bq[4][2];
    #pragma unroll
    for (int ni = 0; ni < 4; ++ni) {
        int n0 = warpN * 32 + ni * 8 + kq * 2;
        bq[ni][0] = __bfloat162float(__float2bfloat16(__ldg(bias + n0)));
        bq[ni][1] = __bfloat162float(__float2bfloat16(__ldg(bias + n0 + 1)));
    }

    // per-lane A base address for each of the 2 m16 tiles (all offsets are
    // compile-time constants after full unroll: + (kh*58+kw)*144 + ks*32)
    uint32_t abase[2];
    #pragma unroll
    for (int mi = 0; mi < 2; ++mi) {
        int p = warpM * 32 + mi * 16 + rl;
        int l = (p / 56) * 58 + (p % 56);
        abase[mi] = insm32 + l * LINE_B + hi16;
    }

    float acc[2][4][4];
    #pragma unroll
    for (int mi = 0; mi < 2; ++mi)
        #pragma unroll
        for (int ni = 0; ni < 4; ++ni)
            #pragma unroll
            for (int q = 0; q < 4; ++q) acc[mi][ni][q] = 0.f;

    asm volatile("cp.async.wait_group 0;\n" ::: "memory");
    __syncthreads();

    // ---- main loop: fully unrolled 9 taps x 4 k16-steps ---------------------
    // All shared-memory addresses are base-register + immediate after unroll.
    #pragma unroll
    for (int kk = 0; kk < 9; ++kk) {
        const int aoff = (kk / 3) * (58 * LINE_B) + (kk % 3) * LINE_B;
        #pragma unroll
        for (int ks = 0; ks < 4; ++ks) {
            // B fragments: two conflict-free LDS.128 cover the 32-n warp tile
            const uint32_t* bp = wfrW + (kk * 4 + ks) * 1024;
            uint4 B0 = *(const uint4*)bp;            // n [warpN*32,    +16)
            uint4 B1 = *(const uint4*)(bp + 128);    // n [warpN*32+16, +16)

            uint32_t a[2][4];
            #pragma unroll
            for (int mi = 0; mi < 2; ++mi) {
                asm("ldmatrix.sync.aligned.m8n8.x4.shared.b16 {%0,%1,%2,%3}, [%4];\n"
                    : "=r"(a[mi][0]), "=r"(a[mi][1]), "=r"(a[mi][2]), "=r"(a[mi][3])
                    : "r"(abase[mi] + aoff + ks * 32));
            }
            #pragma unroll
            for (int mi = 0; mi < 2; ++mi) {
                #define MMA(NI, BX, BY)                                          \
                    asm("mma.sync.aligned.m16n8k16.row.col.f32.bf16.bf16.f32 "   \
                        "{%0,%1,%2,%3}, {%4,%5,%6,%7}, {%8,%9}, {%0,%1,%2,%3};\n"\
                        : "+f"(acc[mi][NI][0]), "+f"(acc[mi][NI][1]),            \
                          "+f"(acc[mi][NI][2]), "+f"(acc[mi][NI][3])             \
                        : "r"(a[mi][0]), "r"(a[mi][1]), "r"(a[mi][2]),           \
                          "r"(a[mi][3]), "r"(BX), "r"(BY))
                MMA(0, B0.x, B0.y);
                MMA(1, B0.z, B0.w);
                MMA(2, B1.x, B1.y);
                MMA(3, B1.z, B1.w);
                #undef MMA
            }
        }
    }

    // ---- epilogue: + bf16(bias), NCHW store --------------------------------
    float* outb = out + (size_t)b * NOUT * IMG + ty * 224;
    #pragma unroll
    for (int ni = 0; ni < 4; ++ni) {
        int n0 = warpN * 32 + ni * 8 + kq * 2;
        float* o0 = outb + (size_t)n0 * IMG;
        float* o1 = o0 + IMG;
        #pragma unroll
        for (int mi = 0; mi < 2; ++mi) {
            int p0 = warpM * 32 + mi * 16 + g;
            o0[p0]     = acc[mi][ni][0] + bq[ni][0];
            o1[p0]     = acc[mi][ni][1] + bq[ni][1];
            o0[p0 + 8] = acc[mi][ni][2] + bq[ni][0];
            o1[p0 + 8] = acc[mi][ni][3] + bq[ni][1];
        }
    }
}

extern "C" void kernel_launch(void* const* d_in, const int* in_sizes, int n_in,
                              void* d_out, int out_size) {
    const float* in   = (const float*)d_in[0];
    const float* w    = (const float*)d_in[1];
    const float* bias = (const float*)d_in[2];
    float* out = (float*)d_out;

    cudaFuncSetAttribute(conv_kernel,
                         cudaFuncAttributeMaxDynamicSharedMemorySize, SMEM_TOTAL);

    wprep_kernel<<<(WFRAG_U32 + 255) / 256, 256>>>(w);
    conv_kernel<<<dim3(14, BATCH), THREADS, SMEM_TOTAL>>>(in, bias, out);
}